// round 6
// baseline (speedup 1.0000x reference)
#include <cuda_runtime.h>
#include <math.h>

#define DMAX   256
#define NMAX   50000
#define TMAX   400000
#define RMAX   1000
#define DEPMAX 2

// ---------------- static device scratch (no allocation allowed) ----------------
__device__ __align__(16) float g_xA[(size_t)NMAX * DMAX];   // 51.2 MB
__device__ __align__(16) float g_xB[(size_t)NMAX * DMAX];   // 51.2 MB
__device__ __align__(16) float g_nrel[(size_t)RMAX * DMAX]; // 1 MB
__device__ float g_attrel[DEPMAX * RMAX];
__device__ int   g_counts[NMAX + 1];
__device__ int   g_rowptr[NMAX + 1];
__device__ int   g_cursor[NMAX];
__device__ int   g_srcp[TMAX];
__device__ int   g_relcode[TMAX];   // permuted by CSR: 0 = zero tri_rel, else +-(rel+1)
__device__ int   g_tricode[TMAX];   // per-triple code before CSR permutation
__device__ int   g_flag64;          // 1 if index arrays are int64, 0 if int32

// ---------------- helpers ----------------
__device__ __forceinline__ long long ld_idx(const void* p, long long i) {
    return g_flag64 ? ((const long long*)p)[i] : (long long)((const int*)p)[i];
}

__device__ __forceinline__ float blockReduce256(float v, float* sm) {
    #pragma unroll
    for (int off = 16; off; off >>= 1) v += __shfl_xor_sync(0xffffffffu, v, off);
    int w = threadIdx.x >> 5;
    if ((threadIdx.x & 31) == 0) sm[w] = v;
    __syncthreads();
    if (threadIdx.x < 32) {
        float r = (threadIdx.x < 8) ? sm[threadIdx.x] : 0.0f;
        #pragma unroll
        for (int off = 4; off; off >>= 1) r += __shfl_xor_sync(0xffffffffu, r, off);
        if (threadIdx.x == 0) sm[0] = r;
    }
    __syncthreads();
    float res = sm[0];
    __syncthreads();
    return res;
}

// ---------------- kernels ----------------

// Detect whether index inputs are int64 or int32 (jax x64 may be disabled).
__global__ void k_detect(const void* adj, int T, int N) {
    const long long* p = (const long long*)adj;
    int is64 = 1;
    int lim = (T < 32) ? T : 32;
    for (int i = 0; i < lim; i++) {
        long long v = p[i];
        if (v < 0 || v >= (long long)N) { is64 = 0; break; }
    }
    g_flag64 = is64;
}

__global__ void k_zero(int T, int N) {
    int i = blockIdx.x * blockDim.x + threadIdx.x;
    if (i < T) g_tricode[i] = 0;
    if (i <= N) g_counts[i] = 0;
    if (i < N) g_cursor[i] = 0;
}

// tri_rel[seg] = r_val[t] * rel_emb[r_index_rel[t]]  (one contribution per segment)
__global__ void k_scatter_tri(const void* r_tri, const void* r_rel,
                              const float* __restrict__ r_val, int T) {
    int t = blockIdx.x * blockDim.x + threadIdx.x;
    if (t >= T) return;
    long long seg = ld_idx(r_tri, t);
    long long rel = ld_idx(r_rel, t);
    float v = r_val[t];
    int code = 0;
    if (v > 0.0f)      code =  (int)rel + 1;
    else if (v < 0.0f) code = -((int)rel + 1);
    if (seg >= 0 && seg < T) g_tricode[seg] = code;
}

__global__ void k_hist(const void* adj, int T) {
    int t = blockIdx.x * blockDim.x + threadIdx.x;
    if (t >= T) return;
    long long dst = ld_idx(adj, t);
    atomicAdd(&g_counts[(int)dst], 1);
}

// single-block exclusive scan over counts -> rowptr
__global__ void k_scan(int N) {
    __shared__ int sm[1024];
    int tid = threadIdx.x;
    int chunk = (N + 1023) >> 10;
    int base = tid * chunk;
    int s = 0;
    for (int i = 0; i < chunk; i++) { int j = base + i; if (j < N) s += g_counts[j]; }
    sm[tid] = s;
    __syncthreads();
    for (int off = 1; off < 1024; off <<= 1) {
        int v = (tid >= off) ? sm[tid - off] : 0;
        __syncthreads();
        sm[tid] += v;
        __syncthreads();
    }
    int run = tid ? sm[tid - 1] : 0;
    for (int i = 0; i < chunk; i++) {
        int j = base + i;
        if (j < N) { g_rowptr[j] = run; run += g_counts[j]; }
    }
    if (tid == 0) g_rowptr[N] = sm[1023];
}

__global__ void k_place(const void* adj, int T) {
    int t = blockIdx.x * blockDim.x + threadIdx.x;
    if (t >= T) return;
    int dst = (int)ld_idx(adj, t);
    int src = (int)ld_idx(adj, (long long)T + t);
    int pos = g_rowptr[dst] + atomicAdd(&g_cursor[dst], 1);
    g_srcp[pos]    = src;
    g_relcode[pos] = g_tricode[t];
}

// L2-normalize rel_emb rows; precompute per-relation attention logits per layer.
__global__ void k_normalize(const float* __restrict__ rel_emb,
                            const float* __restrict__ attnk, int depth) {
    __shared__ float sm[32];
    int r = blockIdx.x;
    int d = threadIdx.x;
    float v = rel_emb[(size_t)r * DMAX + d];
    float ss = blockReduce256(v * v, sm);
    float scale = 1.0f / fmaxf(sqrtf(ss), 1e-12f);
    float nv = v * scale;
    g_nrel[(size_t)r * DMAX + d] = nv;
    for (int l = 0; l < depth; l++) {
        float a = blockReduce256(nv * attnk[(size_t)l * DMAX + d], sm);
        if (d == 0) g_attrel[l * RMAX + r] = a;
    }
}

// x0 = tanh(features); write both to ping buffer and output slice 0.
__global__ void k_tanh0(const float* __restrict__ f, float* __restrict__ out,
                        int N, int outd) {
    int i = blockIdx.x * blockDim.x + threadIdx.x;
    if (i >= N * DMAX) return;
    float t = tanhf(f[i]);
    g_xA[i] = t;
    out[(size_t)(i >> 8) * outd + (i & 255)] = t;
}

// One warp per destination node: segment softmax + reflected weighted aggregation.
__global__ void __launch_bounds__(256)
k_layer(float* __restrict__ out, int outoff, int outd, int N, int l,
        int inbuf_is_B, int write_next) {
    int gw   = (blockIdx.x * blockDim.x + threadIdx.x) >> 5;
    int lane = threadIdx.x & 31;
    if (gw >= N) return;
    const float* __restrict__ xin = inbuf_is_B ? g_xB : g_xA;
    float*       __restrict__ xnx = inbuf_is_B ? g_xA : g_xB;
    const float* __restrict__ attrow = g_attrel + l * RMAX;

    int e0 = g_rowptr[gw], e1 = g_rowptr[gw + 1];
    float a0 = 0, a1 = 0, a2 = 0, a3 = 0, a4 = 0, a5 = 0, a6 = 0, a7 = 0;

    if (e1 > e0) {
        // softmax stats (warp-redundant; segment is tiny and L1-resident)
        float m = -1e30f;
        for (int e = e0; e < e1; e++) {
            int c = g_relcode[e];
            float a = 0.0f;
            if (c != 0) { int r = (c > 0 ? c : -c) - 1; a = attrow[r]; if (c < 0) a = -a; }
            m = fmaxf(m, a);
        }
        float ssum = 0.0f;
        for (int e = e0; e < e1; e++) {
            int c = g_relcode[e];
            float a = 0.0f;
            if (c != 0) { int r = (c > 0 ? c : -c) - 1; a = attrow[r]; if (c < 0) a = -a; }
            ssum += expf(a - m);
        }
        float inv = 1.0f / ssum;

        for (int e = e0; e < e1; e++) {
            int c = g_relcode[e];
            int srow = g_srcp[e];
            int r = -1;
            float a = 0.0f;
            if (c != 0) { r = (c > 0 ? c : -c) - 1; a = attrow[r]; if (c < 0) a = -a; }
            float w = expf(a - m) * inv;

            const float4* xr = (const float4*)(xin + (size_t)srow * DMAX);
            float4 xa = xr[lane];
            float4 xb = xr[32 + lane];

            if (r >= 0) {
                const float4* vr = (const float4*)(g_nrel + (size_t)r * DMAX);
                float4 va = vr[lane];
                float4 vb = vr[32 + lane];
                float p = xa.x * va.x + xa.y * va.y + xa.z * va.z + xa.w * va.w
                        + xb.x * vb.x + xb.y * vb.y + xb.z * vb.z + xb.w * vb.w;
                #pragma unroll
                for (int off = 16; off; off >>= 1) p += __shfl_xor_sync(0xffffffffu, p, off);
                float t2 = 2.0f * p;   // reflection is sign-invariant
                a0 += w * (xa.x - t2 * va.x);
                a1 += w * (xa.y - t2 * va.y);
                a2 += w * (xa.z - t2 * va.z);
                a3 += w * (xa.w - t2 * va.w);
                a4 += w * (xb.x - t2 * vb.x);
                a5 += w * (xb.y - t2 * vb.y);
                a6 += w * (xb.z - t2 * vb.z);
                a7 += w * (xb.w - t2 * vb.w);
            } else {
                a0 += w * xa.x; a1 += w * xa.y; a2 += w * xa.z; a3 += w * xa.w;
                a4 += w * xb.x; a5 += w * xb.y; a6 += w * xb.z; a7 += w * xb.w;
            }
        }
    }

    float4 o1 = make_float4(tanhf(a0), tanhf(a1), tanhf(a2), tanhf(a3));
    float4 o2 = make_float4(tanhf(a4), tanhf(a5), tanhf(a6), tanhf(a7));
    if (write_next) {
        float4* xw = (float4*)(xnx + (size_t)gw * DMAX);
        xw[lane] = o1;
        xw[32 + lane] = o2;
    }
    float4* ow = (float4*)(out + (size_t)gw * outd + outoff);
    ow[lane] = o1;
    ow[32 + lane] = o2;
}

// ---------------- launch ----------------
extern "C" void kernel_launch(void* const* d_in, const int* in_sizes, int n_in,
                              void* d_out, int out_size) {
    const float* features = (const float*)d_in[0];
    const float* rel_emb  = (const float*)d_in[1];
    const float* attnk    = (const float*)d_in[2];
    const float* r_val    = (const float*)d_in[3];
    const void*  adj      = d_in[4];
    const void*  r_tri    = d_in[5];
    const void*  r_rel    = d_in[6];
    float* out = (float*)d_out;

    int N = in_sizes[0] / DMAX;
    int R = in_sizes[1] / DMAX;
    int depth = in_sizes[2] / DMAX;
    int T = in_sizes[3];
    if (N <= 0 || T <= 0) return;
    if (N > NMAX) N = NMAX;
    if (T > TMAX) T = TMAX;
    if (R > RMAX) R = RMAX;
    if (depth > DEPMAX) depth = DEPMAX;
    int outd = (depth + 1) * DMAX;

    k_detect<<<1, 1>>>(adj, T, N);

    int M = (T > N + 1) ? T : (N + 1);
    k_zero<<<(M + 255) / 256, 256>>>(T, N);
    k_scatter_tri<<<(T + 255) / 256, 256>>>(r_tri, r_rel, r_val, T);
    k_hist<<<(T + 255) / 256, 256>>>(adj, T);
    k_scan<<<1, 1024>>>(N);
    k_place<<<(T + 255) / 256, 256>>>(adj, T);
    k_normalize<<<R, 256>>>(rel_emb, attnk, depth);
    k_tanh0<<<((size_t)N * DMAX + 255) / 256, 256>>>(features, out, N, outd);

    int blocks = (int)(((size_t)N * 32 + 255) / 256);
    for (int l = 0; l < depth; l++) {
        int inbuf_is_B = (l & 1);
        int write_next = (l < depth - 1) ? 1 : 0;
        k_layer<<<blocks, 256>>>(out, (l + 1) * DMAX, outd, N, l, inbuf_is_B, write_next);
    }
}

// round 7
// speedup vs baseline: 1.1331x; 1.1331x over previous
#include <cuda_runtime.h>
#include <cuda_fp16.h>
#include <math.h>

#define DMAX   256
#define NMAX   50000
#define TMAX   400000
#define RMAX   1000
#define DEPMAX 2

// ---------------- static device scratch (no allocation allowed) ----------------
__device__ __align__(16) __half g_xA[(size_t)NMAX * DMAX];    // 25.6 MB
__device__ __align__(16) __half g_xB[(size_t)NMAX * DMAX];    // 25.6 MB
__device__ __align__(16) __half g_nrel[(size_t)RMAX * DMAX];  // 512 KB
__device__ float g_attrel[DEPMAX * RMAX];
__device__ float g_w[(size_t)DEPMAX * TMAX];   // per-edge softmax weights per layer
__device__ int   g_counts[NMAX + 1];
__device__ int   g_rowptr[NMAX + 1];
__device__ int   g_cursor[NMAX];
__device__ int   g_srcp[TMAX];
__device__ int   g_reli[TMAX];      // relation index per CSR edge, -1 if zero tri_rel
__device__ int   g_relcode[TMAX];   // signed code per CSR edge: 0 or +-(rel+1)
__device__ int   g_tricode[TMAX];   // per-triple code before CSR permutation
__device__ int   g_flag64;          // 1 if index arrays are int64, 0 if int32

// ---------------- helpers ----------------
__device__ __forceinline__ long long ld_idx(const void* p, long long i) {
    return g_flag64 ? ((const long long*)p)[i] : (long long)((const int*)p)[i];
}

__device__ __forceinline__ float blockReduce256(float v, float* sm) {
    #pragma unroll
    for (int off = 16; off; off >>= 1) v += __shfl_xor_sync(0xffffffffu, v, off);
    int w = threadIdx.x >> 5;
    if ((threadIdx.x & 31) == 0) sm[w] = v;
    __syncthreads();
    if (threadIdx.x < 32) {
        float r = (threadIdx.x < 8) ? sm[threadIdx.x] : 0.0f;
        #pragma unroll
        for (int off = 4; off; off >>= 1) r += __shfl_xor_sync(0xffffffffu, r, off);
        if (threadIdx.x == 0) sm[0] = r;
    }
    __syncthreads();
    float res = sm[0];
    __syncthreads();
    return res;
}

// load 8 halves (one float4) and widen to f32
__device__ __forceinline__ void loadh8(const __half* __restrict__ row, int lane, float f[8]) {
    float4 raw = ((const float4*)row)[lane];
    const __half2* h = (const __half2*)&raw;
    float2 a = __half22float2(h[0]);
    float2 b = __half22float2(h[1]);
    float2 c = __half22float2(h[2]);
    float2 d = __half22float2(h[3]);
    f[0]=a.x; f[1]=a.y; f[2]=b.x; f[3]=b.y; f[4]=c.x; f[5]=c.y; f[6]=d.x; f[7]=d.y;
}

// ---------------- kernels ----------------

// Detect whether index inputs are int64 or int32 (jax x64 may be disabled). Parallel.
__global__ void k_detect(const void* adj, int T, int N) {
    int i = threadIdx.x;
    int lim = (T < 32) ? T : 32;
    int bad = 0;
    if (i < lim) {
        long long v = ((const long long*)adj)[i];
        if (v < 0 || v >= (long long)N) bad = 1;
    }
    unsigned m = __ballot_sync(0xffffffffu, bad);
    if (i == 0) g_flag64 = (m == 0u) ? 1 : 0;
}

__global__ void k_zero(int T, int N) {
    int i = blockIdx.x * blockDim.x + threadIdx.x;
    if (i < T) g_tricode[i] = 0;
    if (i <= N) g_counts[i] = 0;
    if (i < N) g_cursor[i] = 0;
}

// fused: tri_rel scatter code + dst histogram
__global__ void k_prep(const void* r_tri, const void* r_rel,
                       const float* __restrict__ r_val, const void* adj, int T) {
    int t = blockIdx.x * blockDim.x + threadIdx.x;
    if (t >= T) return;
    long long seg = ld_idx(r_tri, t);
    long long rel = ld_idx(r_rel, t);
    float v = r_val[t];
    int code = 0;
    if (v > 0.0f)      code =  (int)rel + 1;
    else if (v < 0.0f) code = -((int)rel + 1);
    if (seg >= 0 && seg < T) g_tricode[seg] = code;
    long long dst = ld_idx(adj, t);
    atomicAdd(&g_counts[(int)dst], 1);
}

// single-block exclusive scan over counts -> rowptr
__global__ void k_scan(int N) {
    __shared__ int sm[1024];
    int tid = threadIdx.x;
    int chunk = (N + 1023) >> 10;
    int base = tid * chunk;
    int s = 0;
    for (int i = 0; i < chunk; i++) { int j = base + i; if (j < N) s += g_counts[j]; }
    sm[tid] = s;
    __syncthreads();
    for (int off = 1; off < 1024; off <<= 1) {
        int v = (tid >= off) ? sm[tid - off] : 0;
        __syncthreads();
        sm[tid] += v;
        __syncthreads();
    }
    int run = tid ? sm[tid - 1] : 0;
    for (int i = 0; i < chunk; i++) {
        int j = base + i;
        if (j < N) { g_rowptr[j] = run; run += g_counts[j]; }
    }
    if (tid == 0) g_rowptr[N] = sm[1023];
}

__global__ void k_place(const void* adj, int T) {
    int t = blockIdx.x * blockDim.x + threadIdx.x;
    if (t >= T) return;
    int dst = (int)ld_idx(adj, t);
    int src = (int)ld_idx(adj, (long long)T + t);
    int pos = g_rowptr[dst] + atomicAdd(&g_cursor[dst], 1);
    g_srcp[pos]    = src;
    g_relcode[pos] = g_tricode[t];
}

// L2-normalize rel_emb rows (f32 math, fp16 store); per-relation attention logits.
__global__ void k_normalize(const float* __restrict__ rel_emb,
                            const float* __restrict__ attnk, int depth) {
    __shared__ float sm[32];
    int r = blockIdx.x;
    int d = threadIdx.x;
    float v = rel_emb[(size_t)r * DMAX + d];
    float ss = blockReduce256(v * v, sm);
    float scale = 1.0f / fmaxf(sqrtf(ss), 1e-12f);
    float nv = v * scale;
    g_nrel[(size_t)r * DMAX + d] = __float2half_rn(nv);
    for (int l = 0; l < depth; l++) {
        float a = blockReduce256(nv * attnk[(size_t)l * DMAX + d], sm);
        if (d == 0) g_attrel[l * RMAX + r] = a;
    }
}

// Precompute per-edge softmax weights for all layers. One warp per dst node.
__global__ void __launch_bounds__(256) k_weights(int N, int T, int depth) {
    int gw   = (blockIdx.x * blockDim.x + threadIdx.x) >> 5;
    int lane = threadIdx.x & 31;
    if (gw >= N) return;
    int e0 = g_rowptr[gw], e1 = g_rowptr[gw + 1];
    if (e0 >= e1) return;

    for (int e = e0 + lane; e < e1; e += 32) {
        int c = g_relcode[e];
        g_reli[e] = c ? ((c > 0 ? c : -c) - 1) : -1;
    }

    for (int l = 0; l < depth; l++) {
        const float* __restrict__ ar = g_attrel + l * RMAX;
        float m = -1e30f, s = 0.0f;
        for (int base = e0; base < e1; base += 32) {
            int e = base + lane;
            bool valid = e < e1;
            float a = 0.0f;
            if (valid) {
                int c = g_relcode[e];
                if (c) { int r = (c > 0 ? c : -c) - 1; a = ar[r]; if (c < 0) a = -a; }
            }
            float am = valid ? a : -1e30f;
            #pragma unroll
            for (int off = 16; off; off >>= 1) am = fmaxf(am, __shfl_xor_sync(0xffffffffu, am, off));
            float nm = fmaxf(m, am);
            float ex = valid ? expf(a - nm) : 0.0f;
            #pragma unroll
            for (int off = 16; off; off >>= 1) ex += __shfl_xor_sync(0xffffffffu, ex, off);
            s = s * expf(m - nm) + ex;
            m = nm;
        }
        float inv = 1.0f / s;
        for (int base = e0; base < e1; base += 32) {
            int e = base + lane;
            if (e < e1) {
                int c = g_relcode[e];
                float a = 0.0f;
                if (c) { int r = (c > 0 ? c : -c) - 1; a = ar[r]; if (c < 0) a = -a; }
                g_w[(size_t)l * T + e] = expf(a - m) * inv;
            }
        }
    }
}

// x0 = tanh(features); fp16 to ping buffer, exact f32 to output slice 0.
__global__ void k_tanh0(const float* __restrict__ f, float* __restrict__ out,
                        int N, int outd) {
    int i = blockIdx.x * blockDim.x + threadIdx.x;
    if (i >= N * DMAX) return;
    float t = tanhf(f[i]);
    g_xA[i] = __float2half_rn(t);
    out[(size_t)(i >> 8) * outd + (i & 255)] = t;
}

// One warp per destination node: reflected weighted aggregation (weights precomputed).
__global__ void __launch_bounds__(256)
k_layer(float* __restrict__ out, int outoff, int outd, int N, int T, int l,
        int inbuf_is_B, int write_next) {
    int gw   = (blockIdx.x * blockDim.x + threadIdx.x) >> 5;
    int lane = threadIdx.x & 31;
    if (gw >= N) return;
    const __half* __restrict__ xin = inbuf_is_B ? g_xB : g_xA;
    __half*       __restrict__ xnx = inbuf_is_B ? g_xA : g_xB;
    const float*  __restrict__ wrow = g_w + (size_t)l * T;

    int e0 = g_rowptr[gw], e1 = g_rowptr[gw + 1];
    float acc[8] = {0, 0, 0, 0, 0, 0, 0, 0};

    int e = e0;
    // 2-way unrolled: overlap the two SHFL dot-reduction chains
    for (; e + 1 < e1; e += 2) {
        int r0 = g_reli[e],     s0 = g_srcp[e];     float w0 = wrow[e];
        int r1 = g_reli[e + 1], s1 = g_srcp[e + 1]; float w1 = wrow[e + 1];
        float x0[8], x1[8];
        loadh8(xin + (size_t)s0 * DMAX, lane, x0);
        loadh8(xin + (size_t)s1 * DMAX, lane, x1);
        float v0[8], v1[8];
        float p0 = 0.0f, p1 = 0.0f;
        if (r0 >= 0) {
            loadh8(g_nrel + (size_t)r0 * DMAX, lane, v0);
            #pragma unroll
            for (int i = 0; i < 8; i++) p0 += x0[i] * v0[i];
        }
        if (r1 >= 0) {
            loadh8(g_nrel + (size_t)r1 * DMAX, lane, v1);
            #pragma unroll
            for (int i = 0; i < 8; i++) p1 += x1[i] * v1[i];
        }
        #pragma unroll
        for (int off = 16; off; off >>= 1) {
            p0 += __shfl_xor_sync(0xffffffffu, p0, off);
            p1 += __shfl_xor_sync(0xffffffffu, p1, off);
        }
        if (r0 >= 0) {
            float t2 = 2.0f * p0;
            #pragma unroll
            for (int i = 0; i < 8; i++) acc[i] += w0 * (x0[i] - t2 * v0[i]);
        } else {
            #pragma unroll
            for (int i = 0; i < 8; i++) acc[i] += w0 * x0[i];
        }
        if (r1 >= 0) {
            float t2 = 2.0f * p1;
            #pragma unroll
            for (int i = 0; i < 8; i++) acc[i] += w1 * (x1[i] - t2 * v1[i]);
        } else {
            #pragma unroll
            for (int i = 0; i < 8; i++) acc[i] += w1 * x1[i];
        }
    }
    for (; e < e1; e++) {
        int r = g_reli[e], srow = g_srcp[e];
        float w = wrow[e];
        float x[8];
        loadh8(xin + (size_t)srow * DMAX, lane, x);
        if (r >= 0) {
            float v[8];
            loadh8(g_nrel + (size_t)r * DMAX, lane, v);
            float p = 0.0f;
            #pragma unroll
            for (int i = 0; i < 8; i++) p += x[i] * v[i];
            #pragma unroll
            for (int off = 16; off; off >>= 1) p += __shfl_xor_sync(0xffffffffu, p, off);
            float t2 = 2.0f * p;
            #pragma unroll
            for (int i = 0; i < 8; i++) acc[i] += w * (x[i] - t2 * v[i]);
        } else {
            #pragma unroll
            for (int i = 0; i < 8; i++) acc[i] += w * x[i];
        }
    }

    float o[8];
    #pragma unroll
    for (int i = 0; i < 8; i++) o[i] = tanhf(acc[i]);

    if (write_next) {
        // pack 8 f32 -> 8 halves, one float4 store, same mapping as the load
        float4 hraw;
        __half2* hh = (__half2*)&hraw;
        hh[0] = __floats2half2_rn(o[0], o[1]);
        hh[1] = __floats2half2_rn(o[2], o[3]);
        hh[2] = __floats2half2_rn(o[4], o[5]);
        hh[3] = __floats2half2_rn(o[6], o[7]);
        ((float4*)(xnx + (size_t)gw * DMAX))[lane] = hraw;
    }
    // f32 output: dims [8*lane, 8*lane+7] -> float4 slots 2*lane and 2*lane+1
    float4* ow = (float4*)(out + (size_t)gw * outd + outoff);
    ow[2 * lane]     = make_float4(o[0], o[1], o[2], o[3]);
    ow[2 * lane + 1] = make_float4(o[4], o[5], o[6], o[7]);
}

// ---------------- launch ----------------
extern "C" void kernel_launch(void* const* d_in, const int* in_sizes, int n_in,
                              void* d_out, int out_size) {
    const float* features = (const float*)d_in[0];
    const float* rel_emb  = (const float*)d_in[1];
    const float* attnk    = (const float*)d_in[2];
    const float* r_val    = (const float*)d_in[3];
    const void*  adj      = d_in[4];
    const void*  r_tri    = d_in[5];
    const void*  r_rel    = d_in[6];
    float* out = (float*)d_out;

    int N = in_sizes[0] / DMAX;
    int R = in_sizes[1] / DMAX;
    int depth = in_sizes[2] / DMAX;
    int T = in_sizes[3];
    if (N <= 0 || T <= 0) return;
    if (N > NMAX) N = NMAX;
    if (T > TMAX) T = TMAX;
    if (R > RMAX) R = RMAX;
    if (depth > DEPMAX) depth = DEPMAX;
    int outd = (depth + 1) * DMAX;

    k_detect<<<1, 32>>>(adj, T, N);

    int M = (T > N + 1) ? T : (N + 1);
    k_zero<<<(M + 255) / 256, 256>>>(T, N);
    k_prep<<<(T + 255) / 256, 256>>>(r_tri, r_rel, r_val, adj, T);
    k_scan<<<1, 1024>>>(N);
    k_place<<<(T + 255) / 256, 256>>>(adj, T);
    k_normalize<<<R, 256>>>(rel_emb, attnk, depth);

    int wblocks = (int)(((size_t)N * 32 + 255) / 256);
    k_weights<<<wblocks, 256>>>(N, T, depth);
    k_tanh0<<<((size_t)N * DMAX + 255) / 256, 256>>>(features, out, N, outd);

    for (int l = 0; l < depth; l++) {
        int inbuf_is_B = (l & 1);
        int write_next = (l < depth - 1) ? 1 : 0;
        k_layer<<<wblocks, 256>>>(out, (l + 1) * DMAX, outd, N, T, l, inbuf_is_B, write_next);
    }
}

// round 8
// speedup vs baseline: 1.3228x; 1.1675x over previous
#include <cuda_runtime.h>
#include <cuda_fp16.h>
#include <math.h>

#define DMAX   256
#define NMAX   50000
#define TMAX   400000
#define RMAX   1000
#define DEPMAX 2
#define SCAN_CHUNK 2048   // elements per scan block (256 thr * 8)

// ---------------- static device scratch (no allocation allowed) ----------------
__device__ __align__(16) __half g_xA[(size_t)NMAX * DMAX];    // 25.6 MB
__device__ __align__(16) __half g_xB[(size_t)NMAX * DMAX];    // 25.6 MB
__device__ __align__(16) __half g_nrel[(size_t)RMAX * DMAX];  // 512 KB
__device__ float g_attrel[DEPMAX * RMAX];
__device__ float g_w[(size_t)DEPMAX * TMAX];   // per-edge softmax weights per layer
__device__ int   g_counts[NMAX + 1];
__device__ int   g_rowptr[NMAX + 1];
__device__ int   g_cursor[NMAX];
__device__ int   g_bsum[64];
__device__ int   g_bpre[64];
__device__ int   g_srcp[TMAX];
__device__ int   g_reli[TMAX];      // relation index per CSR edge, -1 if zero tri_rel
__device__ int   g_relcode[TMAX];   // signed code per CSR edge: 0 or +-(rel+1)
__device__ int   g_tricode[TMAX];   // per-triple code before CSR permutation
__device__ int   g_flag64;          // 1 if index arrays are int64, 0 if int32

// ---------------- helpers ----------------
__device__ __forceinline__ long long ld_idx(const void* p, long long i) {
    return g_flag64 ? ((const long long*)p)[i] : (long long)((const int*)p)[i];
}

__device__ __forceinline__ float blockReduce256(float v, float* sm) {
    #pragma unroll
    for (int off = 16; off; off >>= 1) v += __shfl_xor_sync(0xffffffffu, v, off);
    int w = threadIdx.x >> 5;
    if ((threadIdx.x & 31) == 0) sm[w] = v;
    __syncthreads();
    if (threadIdx.x < 32) {
        float r = (threadIdx.x < 8) ? sm[threadIdx.x] : 0.0f;
        #pragma unroll
        for (int off = 4; off; off >>= 1) r += __shfl_xor_sync(0xffffffffu, r, off);
        if (threadIdx.x == 0) sm[0] = r;
    }
    __syncthreads();
    float res = sm[0];
    __syncthreads();
    return res;
}

// load 8 halves (one float4) and widen to f32
__device__ __forceinline__ void loadh8(const __half* __restrict__ row, int lane, float f[8]) {
    float4 raw = ((const float4*)row)[lane];
    const __half2* h = (const __half2*)&raw;
    float2 a = __half22float2(h[0]);
    float2 b = __half22float2(h[1]);
    float2 c = __half22float2(h[2]);
    float2 d = __half22float2(h[3]);
    f[0]=a.x; f[1]=a.y; f[2]=b.x; f[3]=b.y; f[4]=c.x; f[5]=c.y; f[6]=d.x; f[7]=d.y;
}

// ---------------- kernels ----------------

// Detect whether index inputs are int64 or int32 (jax x64 may be disabled). Parallel.
__global__ void k_detect(const void* adj, int T, int N) {
    int i = threadIdx.x;
    int lim = (T < 32) ? T : 32;
    int bad = 0;
    if (i < lim) {
        long long v = ((const long long*)adj)[i];
        if (v < 0 || v >= (long long)N) bad = 1;
    }
    unsigned m = __ballot_sync(0xffffffffu, bad);
    if (i == 0) g_flag64 = (m == 0u) ? 1 : 0;
}

__global__ void k_zero(int T, int N) {
    int i = blockIdx.x * blockDim.x + threadIdx.x;
    if (i < T) g_tricode[i] = 0;
    if (i <= N) g_counts[i] = 0;
    if (i < N) g_cursor[i] = 0;
}

// fused: tri_rel scatter code + dst histogram
__global__ void k_prep(const void* r_tri, const void* r_rel,
                       const float* __restrict__ r_val, const void* adj, int T) {
    int t = blockIdx.x * blockDim.x + threadIdx.x;
    if (t >= T) return;
    long long seg = ld_idx(r_tri, t);
    long long rel = ld_idx(r_rel, t);
    float v = r_val[t];
    int code = 0;
    if (v > 0.0f)      code =  (int)rel + 1;
    else if (v < 0.0f) code = -((int)rel + 1);
    if (seg >= 0 && seg < T) g_tricode[seg] = code;
    long long dst = ld_idx(adj, t);
    atomicAdd(&g_counts[(int)dst], 1);
}

// ---- 3-phase full-chip exclusive scan of g_counts -> g_rowptr ----
__global__ void k_scan1(int N) {
    __shared__ int warpsum[8];
    int tid = threadIdx.x;
    int base = blockIdx.x * SCAN_CHUNK + tid * 8;
    int v[8];
    #pragma unroll
    for (int i = 0; i < 8; i++) {
        int j = base + i;
        v[i] = (j < N) ? g_counts[j] : 0;
    }
    int pref[8];
    int s = 0;
    #pragma unroll
    for (int i = 0; i < 8; i++) { pref[i] = s; s += v[i]; }
    int lane = tid & 31, w = tid >> 5;
    // warp inclusive scan of per-thread sums
    int inc = s;
    #pragma unroll
    for (int off = 1; off < 32; off <<= 1) {
        int t = __shfl_up_sync(0xffffffffu, inc, off);
        if (lane >= off) inc += t;
    }
    if (lane == 31) warpsum[w] = inc;
    __syncthreads();
    int woff = 0;
    if (w > 0) {
        // small serial sum of up to 7 warp totals (in smem, cheap)
        #pragma unroll
        for (int k = 0; k < 7; k++) if (k < w) woff += warpsum[k];
    }
    int toff = woff + inc - s;   // exclusive offset of this thread within block
    #pragma unroll
    for (int i = 0; i < 8; i++) {
        int j = base + i;
        if (j < N) g_rowptr[j] = toff + pref[i];
    }
    if (tid == 255) g_bsum[blockIdx.x] = woff + inc;  // block total
}

__global__ void k_scan2(int nb, int N) {
    int b = threadIdx.x;
    int v = (b < nb) ? g_bsum[b] : 0;
    int orig = v;
    #pragma unroll
    for (int off = 1; off < 32; off <<= 1) {
        int t = __shfl_up_sync(0xffffffffu, v, off);
        if (b >= off) v += t;
    }
    if (b < nb) g_bpre[b] = v - orig;          // exclusive block offset
    if (b == nb - 1) g_rowptr[N] = v;          // grand total
}

__global__ void k_scan3(int N) {
    int j = blockIdx.x * blockDim.x + threadIdx.x;
    if (j < N) g_rowptr[j] += g_bpre[j / SCAN_CHUNK];
}

__global__ void k_place(const void* adj, int T) {
    int t = blockIdx.x * blockDim.x + threadIdx.x;
    if (t >= T) return;
    int dst = (int)ld_idx(adj, t);
    int src = (int)ld_idx(adj, (long long)T + t);
    int pos = g_rowptr[dst] + atomicAdd(&g_cursor[dst], 1);
    int c = g_tricode[t];
    g_srcp[pos]    = src;
    g_relcode[pos] = c;
    g_reli[pos]    = c ? ((c > 0 ? c : -c) - 1) : -1;
}

// L2-normalize rel_emb rows (f32 math, fp16 store); per-relation attention logits.
__global__ void k_normalize(const float* __restrict__ rel_emb,
                            const float* __restrict__ attnk, int depth) {
    __shared__ float sm[32];
    int r = blockIdx.x;
    int d = threadIdx.x;
    float v = rel_emb[(size_t)r * DMAX + d];
    float ss = blockReduce256(v * v, sm);
    float scale = 1.0f / fmaxf(sqrtf(ss), 1e-12f);
    float nv = v * scale;
    g_nrel[(size_t)r * DMAX + d] = __float2half_rn(nv);
    for (int l = 0; l < depth; l++) {
        float a = blockReduce256(nv * attnk[(size_t)l * DMAX + d], sm);
        if (d == 0) g_attrel[l * RMAX + r] = a;
    }
}

// Precompute per-edge softmax weights for all layers. One warp per dst node.
__global__ void __launch_bounds__(256) k_weights(int N, int T, int depth) {
    int gw   = (blockIdx.x * blockDim.x + threadIdx.x) >> 5;
    int lane = threadIdx.x & 31;
    if (gw >= N) return;
    int e0 = g_rowptr[gw], e1 = g_rowptr[gw + 1];
    if (e0 >= e1) return;

    for (int l = 0; l < depth; l++) {
        const float* __restrict__ ar = g_attrel + l * RMAX;
        float m = -1e30f, s = 0.0f;
        for (int base = e0; base < e1; base += 32) {
            int e = base + lane;
            bool valid = e < e1;
            float a = 0.0f;
            if (valid) {
                int c = g_relcode[e];
                if (c) { int r = (c > 0 ? c : -c) - 1; a = ar[r]; if (c < 0) a = -a; }
            }
            float am = valid ? a : -1e30f;
            #pragma unroll
            for (int off = 16; off; off >>= 1) am = fmaxf(am, __shfl_xor_sync(0xffffffffu, am, off));
            float nm = fmaxf(m, am);
            float ex = valid ? expf(a - nm) : 0.0f;
            #pragma unroll
            for (int off = 16; off; off >>= 1) ex += __shfl_xor_sync(0xffffffffu, ex, off);
            s = s * expf(m - nm) + ex;
            m = nm;
        }
        float inv = 1.0f / s;
        for (int base = e0; base < e1; base += 32) {
            int e = base + lane;
            if (e < e1) {
                int c = g_relcode[e];
                float a = 0.0f;
                if (c) { int r = (c > 0 ? c : -c) - 1; a = ar[r]; if (c < 0) a = -a; }
                g_w[(size_t)l * T + e] = expf(a - m) * inv;
            }
        }
    }
}

// x0 = tanh(features); fp16 to ping buffer, exact f32 to output slice 0.
__global__ void k_tanh0(const float* __restrict__ f, float* __restrict__ out,
                        int N, int outd) {
    int i = blockIdx.x * blockDim.x + threadIdx.x;
    if (i >= N * DMAX) return;
    float t = tanhf(f[i]);
    g_xA[i] = __float2half_rn(t);
    out[(size_t)(i >> 8) * outd + (i & 255)] = t;
}

// One warp per destination node: reflected weighted aggregation (weights precomputed).
__global__ void __launch_bounds__(256)
k_layer(float* __restrict__ out, int outoff, int outd, int N, int T, int l,
        int inbuf_is_B, int write_next) {
    int gw   = (blockIdx.x * blockDim.x + threadIdx.x) >> 5;
    int lane = threadIdx.x & 31;
    if (gw >= N) return;
    const __half* __restrict__ xin = inbuf_is_B ? g_xB : g_xA;
    __half*       __restrict__ xnx = inbuf_is_B ? g_xA : g_xB;
    const float*  __restrict__ wrow = g_w + (size_t)l * T;

    int e0 = g_rowptr[gw], e1 = g_rowptr[gw + 1];
    float acc[8] = {0, 0, 0, 0, 0, 0, 0, 0};

    int e = e0;
    // 2-way unrolled: overlap the two SHFL dot-reduction chains
    for (; e + 1 < e1; e += 2) {
        int r0 = g_reli[e],     s0 = g_srcp[e];     float w0 = wrow[e];
        int r1 = g_reli[e + 1], s1 = g_srcp[e + 1]; float w1 = wrow[e + 1];
        float x0[8], x1[8];
        loadh8(xin + (size_t)s0 * DMAX, lane, x0);
        loadh8(xin + (size_t)s1 * DMAX, lane, x1);
        float v0[8], v1[8];
        float p0 = 0.0f, p1 = 0.0f;
        if (r0 >= 0) {
            loadh8(g_nrel + (size_t)r0 * DMAX, lane, v0);
            #pragma unroll
            for (int i = 0; i < 8; i++) p0 += x0[i] * v0[i];
        }
        if (r1 >= 0) {
            loadh8(g_nrel + (size_t)r1 * DMAX, lane, v1);
            #pragma unroll
            for (int i = 0; i < 8; i++) p1 += x1[i] * v1[i];
        }
        #pragma unroll
        for (int off = 16; off; off >>= 1) {
            p0 += __shfl_xor_sync(0xffffffffu, p0, off);
            p1 += __shfl_xor_sync(0xffffffffu, p1, off);
        }
        if (r0 >= 0) {
            float t2 = 2.0f * p0;
            #pragma unroll
            for (int i = 0; i < 8; i++) acc[i] += w0 * (x0[i] - t2 * v0[i]);
        } else {
            #pragma unroll
            for (int i = 0; i < 8; i++) acc[i] += w0 * x0[i];
        }
        if (r1 >= 0) {
            float t2 = 2.0f * p1;
            #pragma unroll
            for (int i = 0; i < 8; i++) acc[i] += w1 * (x1[i] - t2 * v1[i]);
        } else {
            #pragma unroll
            for (int i = 0; i < 8; i++) acc[i] += w1 * x1[i];
        }
    }
    for (; e < e1; e++) {
        int r = g_reli[e], srow = g_srcp[e];
        float w = wrow[e];
        float x[8];
        loadh8(xin + (size_t)srow * DMAX, lane, x);
        if (r >= 0) {
            float v[8];
            loadh8(g_nrel + (size_t)r * DMAX, lane, v);
            float p = 0.0f;
            #pragma unroll
            for (int i = 0; i < 8; i++) p += x[i] * v[i];
            #pragma unroll
            for (int off = 16; off; off >>= 1) p += __shfl_xor_sync(0xffffffffu, p, off);
            float t2 = 2.0f * p;
            #pragma unroll
            for (int i = 0; i < 8; i++) acc[i] += w * (x[i] - t2 * v[i]);
        } else {
            #pragma unroll
            for (int i = 0; i < 8; i++) acc[i] += w * x[i];
        }
    }

    float o[8];
    #pragma unroll
    for (int i = 0; i < 8; i++) o[i] = tanhf(acc[i]);

    if (write_next) {
        float4 hraw;
        __half2* hh = (__half2*)&hraw;
        hh[0] = __floats2half2_rn(o[0], o[1]);
        hh[1] = __floats2half2_rn(o[2], o[3]);
        hh[2] = __floats2half2_rn(o[4], o[5]);
        hh[3] = __floats2half2_rn(o[6], o[7]);
        ((float4*)(xnx + (size_t)gw * DMAX))[lane] = hraw;
    }
    float4* ow = (float4*)(out + (size_t)gw * outd + outoff);
    ow[2 * lane]     = make_float4(o[0], o[1], o[2], o[3]);
    ow[2 * lane + 1] = make_float4(o[4], o[5], o[6], o[7]);
}

// ---------------- launch ----------------
extern "C" void kernel_launch(void* const* d_in, const int* in_sizes, int n_in,
                              void* d_out, int out_size) {
    const float* features = (const float*)d_in[0];
    const float* rel_emb  = (const float*)d_in[1];
    const float* attnk    = (const float*)d_in[2];
    const float* r_val    = (const float*)d_in[3];
    const void*  adj      = d_in[4];
    const void*  r_tri    = d_in[5];
    const void*  r_rel    = d_in[6];
    float* out = (float*)d_out;

    int N = in_sizes[0] / DMAX;
    int R = in_sizes[1] / DMAX;
    int depth = in_sizes[2] / DMAX;
    int T = in_sizes[3];
    if (N <= 0 || T <= 0) return;
    if (N > NMAX) N = NMAX;
    if (T > TMAX) T = TMAX;
    if (R > RMAX) R = RMAX;
    if (depth > DEPMAX) depth = DEPMAX;
    int outd = (depth + 1) * DMAX;

    k_detect<<<1, 32>>>(adj, T, N);

    int M = (T > N + 1) ? T : (N + 1);
    k_zero<<<(M + 255) / 256, 256>>>(T, N);
    k_prep<<<(T + 255) / 256, 256>>>(r_tri, r_rel, r_val, adj, T);

    int nb = (N + SCAN_CHUNK - 1) / SCAN_CHUNK;   // <= 25 for NMAX
    k_scan1<<<nb, 256>>>(N);
    k_scan2<<<1, 32>>>(nb, N);
    k_scan3<<<(N + 255) / 256, 256>>>(N);

    k_place<<<(T + 255) / 256, 256>>>(adj, T);
    k_normalize<<<R, 256>>>(rel_emb, attnk, depth);

    int wblocks = (int)(((size_t)N * 32 + 255) / 256);
    k_weights<<<wblocks, 256>>>(N, T, depth);
    k_tanh0<<<((size_t)N * DMAX + 255) / 256, 256>>>(features, out, N, outd);

    for (int l = 0; l < depth; l++) {
        int inbuf_is_B = (l & 1);
        int write_next = (l < depth - 1) ? 1 : 0;
        k_layer<<<wblocks, 256>>>(out, (l + 1) * DMAX, outd, N, T, l, inbuf_is_B, write_next);
    }
}